// round 2
// baseline (speedup 1.0000x reference)
#include <cuda_runtime.h>

// Problem constants (from reference)
#define BB 16          // batches
#define NN 576         // queries
#define MM 16          // targets
#define DD 81          // classes / emb dim
#define BG 80
#define IOU_THR 0.75f
#define MARGIN 0.5f
#define NWARPS (NN/32) // 18

// Device-global scratch (no allocations allowed)
__device__ float g_acc[5];      // 0:ce_sum 1:bbox_sum 2:giou_sum 3:pos_sum 4:neg_sum
__device__ int   g_cnt[DD];     // global label histogram
__device__ int   g_tc[BB*NN];   // final labels

__global__ void k_init() {
    int t = threadIdx.x;
    if (t < 5)  g_acc[t] = 0.f;
    if (t < DD) g_cnt[t] = 0;
}

// One block per batch: relabel scan + CE/focal + histogram + bbox/giou
__global__ void __launch_bounds__(NN) k_scan(
    const float* __restrict__ cp,   // class_predictions [B,N,D]
    const float* __restrict__ pb,   // pred_boxes [B,N,4]
    const float* __restrict__ tb,   // target_boxes [B,M,4]
    const int*   __restrict__ tl,   // target_labels [B,M]
    const int*   __restrict__ mi)   // match_idx [B,M]
{
    __shared__ float4 sbox[NN];
    __shared__ float  sarea[NN];
    __shared__ int    tc[NN];
    __shared__ int    scnt[DD];
    __shared__ int    swmin[NWARPS];
    __shared__ int    snext;
    __shared__ float  red[3*NWARPS];

    const int b = blockIdx.x;
    const int j = threadIdx.x;

    float4 box = ((const float4*)pb)[b*NN + j];
    sbox[j]  = box;
    float areaj = (box.z - box.x) * (box.w - box.y);
    sarea[j] = areaj;
    tc[j] = BG;
    if (j < DD) scnt[j] = 0;
    __syncthreads();

    // tc0: scatter target labels (last index wins, sequential order)
    if (j == 0) {
        #pragma unroll
        for (int m = 0; m < MM; m++)
            tc[mi[b*MM + m]] = tl[b*MM + m];
    }
    __syncthreads();

    // Sequential relabel scan, skipping BG steps via parallel min-index search.
    int cur = 0;
    while (true) {
        int cand = (j >= cur && tc[j] != BG) ? j : NN;
        unsigned wmin = __reduce_min_sync(0xffffffffu, (unsigned)cand);
        if ((j & 31) == 0) swmin[j >> 5] = (int)wmin;
        __syncthreads();
        if (j == 0) {
            int m = NN;
            #pragma unroll
            for (int w = 0; w < NWARPS; w++) m = min(m, swmin[w]);
            snext = m;
        }
        __syncthreads();
        int n = snext;
        if (n >= NN) break;

        int label = tc[n];          // only thread n can write tc[n], and with same value
        float4 bn = sbox[n];
        float lx = fmaxf(bn.x, box.x), ly = fmaxf(bn.y, box.y);
        float rx = fminf(bn.z, box.z), ry = fminf(bn.w, box.w);
        float w  = fmaxf(rx - lx, 0.f), h = fmaxf(ry - ly, 0.f);
        float inter = w * h;
        float iou = inter / (sarea[n] + areaj - inter);
        if (iou > IOU_THR) tc[j] = label;   // each thread writes only its own slot
        cur = n + 1;
        __syncthreads();
    }
    __syncthreads();

    // ---- CE / focal loss for this thread's row ----
    int t = tc[j];
    g_tc[b*NN + j] = t;
    atomicAdd(&scnt[t], 1);

    const float* row = cp + (size_t)(b*NN + j) * DD;
    float mx = -3.402823e38f;
    #pragma unroll 9
    for (int c = 0; c < DD; c++) mx = fmaxf(mx, row[c]);
    float se = 0.f;
    #pragma unroll 9
    for (int c = 0; c < DD; c++) se += expf(row[c] - mx);
    float lse = logf(se);
    float ce  = -(row[t] - mx - lse);
    float p   = expf(-ce);
    float fl  = (1.f - p) * (1.f - p) * ce;
    bool  isbg = (t == BG);
    float flbg = isbg ? fl * 0.1f : 0.f;
    float flfg = isbg ? 0.f : fl;
    float cbg  = isbg ? 1.f : 0.f;

    #pragma unroll
    for (int o = 16; o > 0; o >>= 1) {
        flbg += __shfl_down_sync(0xffffffffu, flbg, o);
        flfg += __shfl_down_sync(0xffffffffu, flfg, o);
        cbg  += __shfl_down_sync(0xffffffffu, cbg,  o);
    }
    int wid = j >> 5, lid = j & 31;
    if (lid == 0) {
        red[wid]            = flbg;
        red[NWARPS + wid]   = flfg;
        red[2*NWARPS + wid] = cbg;
    }
    __syncthreads();
    if (j == 0) {
        float sb = 0.f, sf = 0.f, cb = 0.f;
        #pragma unroll
        for (int w2 = 0; w2 < NWARPS; w2++) {
            sb += red[w2]; sf += red[NWARPS + w2]; cb += red[2*NWARPS + w2];
        }
        atomicAdd(&g_acc[0], sb / cb + sf / ((float)NN - cb));
    }
    if (j < DD) atomicAdd(&g_cnt[j], scnt[j]);

    // ---- bbox L1 + GIoU for matched pairs ----
    if (j < MM) {
        int idx = mi[b*MM + j];
        float4 s  = sbox[idx];
        float4 tg = ((const float4*)tb)[b*MM + j];
        float l1 = fabsf(s.x - tg.x) + fabsf(s.y - tg.y)
                 + fabsf(s.z - tg.z) + fabsf(s.w - tg.w);
        float lx = fmaxf(s.x, tg.x), ly = fmaxf(s.y, tg.y);
        float rx = fminf(s.z, tg.z), ry = fminf(s.w, tg.w);
        float w  = fmaxf(rx - lx, 0.f), h = fmaxf(ry - ly, 0.f);
        float inter = w * h;
        float areas = (s.z - s.x) * (s.w - s.y);
        float areat = (tg.z - tg.x) * (tg.w - tg.y);
        float uni = areas + areat - inter;
        float iou = inter / uni;
        float lx2 = fminf(s.x, tg.x), ly2 = fminf(s.y, tg.y);
        float rx2 = fmaxf(s.z, tg.z), ry2 = fmaxf(s.w, tg.w);
        float ac  = (rx2 - lx2) * (ry2 - ly2);
        float giou = iou - (ac - uni) / ac;
        atomicAdd(&g_acc[1], l1);
        atomicAdd(&g_acc[2], 1.f - giou);
    }
}

// Push/pull loss collapsed by label histogram: one thread per embedding row.
__global__ void __launch_bounds__(128) k_push(const float* __restrict__ emb)
{
    __shared__ float scnt[DD];
    __shared__ float redp[4], redn[4];
    int tid = threadIdx.x;
    int i = blockIdx.x * 128 + tid;
    if (tid < DD) scnt[tid] = (float)g_cnt[tid];
    __syncthreads();

    float pos = 0.f, neg = 0.f;
    if (i < BB*NN) {
        const float* row = emb + (size_t)i * DD;
        float ss = 0.f;
        #pragma unroll 9
        for (int c = 0; c < DD; c++) { float v = row[c]; ss += v * v; }
        float inv = 1.0f / fmaxf(sqrtf(ss), 1e-12f);
        int lab = g_tc[i];
        #pragma unroll 9
        for (int c = 0; c < DD; c++) {
            float e = row[c] * inv;
            float w = scnt[c];
            if (c == lab) pos += w * (1.f - e);
            else          neg += w * fmaxf(e - MARGIN, 0.f);
        }
    }
    #pragma unroll
    for (int o = 16; o > 0; o >>= 1) {
        pos += __shfl_down_sync(0xffffffffu, pos, o);
        neg += __shfl_down_sync(0xffffffffu, neg, o);
    }
    if ((tid & 31) == 0) { redp[tid >> 5] = pos; redn[tid >> 5] = neg; }
    __syncthreads();
    if (tid == 0) {
        float p = redp[0] + redp[1] + redp[2] + redp[3];
        float n = redn[0] + redn[1] + redn[2] + redn[3];
        atomicAdd(&g_acc[3], p);
        atomicAdd(&g_acc[4], n);
    }
}

__global__ void k_final(float* __restrict__ out)
{
    double pc = 0.0;
    #pragma unroll 9
    for (int c = 0; c < DD; c++) { double v = (double)g_cnt[c]; pc += v * v; }
    double T  = (double)(BB * NN);
    double nc = T * T - pc;
    out[0] = g_acc[0] / (float)BB;
    out[1] = (float)(((double)g_acc[3] / pc + (double)g_acc[4] / nc) / (double)BB);
    out[2] = g_acc[1] / (float)(BB * MM);
    out[3] = g_acc[2] / (float)(BB * MM);
}

extern "C" void kernel_launch(void* const* d_in, const int* in_sizes, int n_in,
                              void* d_out, int out_size)
{
    const float* emb = (const float*)d_in[0];   // image_embeddings
    const float* cp  = (const float*)d_in[1];   // class_predictions
    const float* pb  = (const float*)d_in[2];   // pred_boxes
    const float* tb  = (const float*)d_in[3];   // target_boxes
    const int*   tl  = (const int*)  d_in[4];   // target_labels
    const int*   mi  = (const int*)  d_in[5];   // match_idx
    float* out = (float*)d_out;

    k_init<<<1, 128>>>();
    k_scan<<<BB, NN>>>(cp, pb, tb, tl, mi);
    k_push<<<(BB*NN + 127) / 128, 128>>>(emb);
    k_final<<<1, 1>>>(out);
}